// round 7
// baseline (speedup 1.0000x reference)
#include <cuda_runtime.h>
#include <cuda_bf16.h>

#define T_DIM 8192

__device__ float        g_scratch = 0.0f;
__device__ unsigned int g_count   = 0u;

// 32-byte aligned pair of float4s: lets ptxas fuse into LDG.256 on sm_103a.
struct alignas(32) f32x8 { float4 lo, hi; };

__global__ void __launch_bounds__(256, 8)
wl_reduce(const f32x8* __restrict__ a, const f32x8* __restrict__ b,
          float* __restrict__ out, int n8, float scale) {
    const int stride = gridDim.x * blockDim.x;
    float acc0 = 0.0f, acc1 = 0.0f;

    for (int i = blockIdx.x * blockDim.x + threadIdx.x; i < n8; i += stride) {
        f32x8 va = a[i];
        f32x8 vb = b[i];

        // t for first element of this 8-group; group never wraps T (8 | 8192).
        float w = (float)(T_DIM - ((i << 3) & (T_DIM - 1)));

        acc0 = fmaf(fabsf(va.lo.x - vb.lo.x), w,        acc0);
        acc0 = fmaf(fabsf(va.lo.y - vb.lo.y), w - 1.0f, acc0);
        acc0 = fmaf(fabsf(va.lo.z - vb.lo.z), w - 2.0f, acc0);
        acc0 = fmaf(fabsf(va.lo.w - vb.lo.w), w - 3.0f, acc0);
        acc1 = fmaf(fabsf(va.hi.x - vb.hi.x), w - 4.0f, acc1);
        acc1 = fmaf(fabsf(va.hi.y - vb.hi.y), w - 5.0f, acc1);
        acc1 = fmaf(fabsf(va.hi.z - vb.hi.z), w - 6.0f, acc1);
        acc1 = fmaf(fabsf(va.hi.w - vb.hi.w), w - 7.0f, acc1);
    }

    float acc = acc0 + acc1;

    #pragma unroll
    for (int o = 16; o > 0; o >>= 1)
        acc += __shfl_down_sync(0xffffffffu, acc, o);

    __shared__ float smem[8];
    const int lane = threadIdx.x & 31;
    const int wid  = threadIdx.x >> 5;
    if (lane == 0) smem[wid] = acc;
    __syncthreads();
    if (wid == 0) {
        acc = (lane < 8) ? smem[lane] : 0.0f;
        #pragma unroll
        for (int o = 4; o > 0; o >>= 1)
            acc += __shfl_down_sync(0xffffffffu, acc, o);

        if (lane == 0) {
            atomicAdd(&g_scratch, acc);
            __threadfence();
            unsigned int old = atomicAdd(&g_count, 1u);
            if (old == gridDim.x - 1) {
                out[0]    = g_scratch * scale;
                g_scratch = 0.0f;
                g_count   = 0u;
            }
        }
    }
}

extern "C" void kernel_launch(void* const* d_in, const int* in_sizes, int n_in,
                              void* d_out, int out_size) {
    const f32x8* y_pred = (const f32x8*)d_in[0];
    const f32x8* y_true = (const f32x8*)d_in[1];
    float* out = (float*)d_out;

    const int n  = in_sizes[0];   // 32*64*8192
    const int n8 = n / 8;

    const double T = (double)T_DIM;
    const double C = 64.0;
    const double B = (double)n / (T * C);
    const float scale = (float)(2.0 / (T * C * (T + 1.0) * B));

    // One full resident wave: 148 SMs x 8 CTAs x 256 thr = 64 warps/SM.
    const int threads = 256;
    int blocks = 148 * 8;
    int max_blocks = (n8 + threads - 1) / threads;
    if (blocks > max_blocks) blocks = max_blocks;

    wl_reduce<<<blocks, threads>>>(y_pred, y_true, out, n8, scale);
}

// round 8
// speedup vs baseline: 1.0153x; 1.0153x over previous
#include <cuda_runtime.h>
#include <cuda_bf16.h>

#define T_DIM 8192

__device__ float        g_scratch = 0.0f;
__device__ unsigned int g_count   = 0u;

__global__ void __launch_bounds__(256, 8)
wl_reduce(const float4* __restrict__ a, const float4* __restrict__ b,
          float* __restrict__ out, int n4, float scale) {
    const int stride = gridDim.x * blockDim.x;
    int i = blockIdx.x * blockDim.x + threadIdx.x;

    float acc0 = 0.0f, acc1 = 0.0f;

    // x2 unroll, strided pair: 4 independent LDG.128 in flight, 32 regs,
    // 8 CTAs/SM (64 warps). Measured best: DRAM 73.1%, 23.84us.
    for (; i + stride < n4; i += 2 * stride) {
        const int j = i + stride;
        float4 a0 = a[i];
        float4 b0 = b[i];
        float4 a1 = a[j];
        float4 b1 = b[j];

        float w0 = (float)(T_DIM - ((i << 2) & (T_DIM - 1)));
        float w1 = (float)(T_DIM - ((j << 2) & (T_DIM - 1)));

        acc0 = fmaf(fabsf(a0.x - b0.x), w0,        acc0);
        acc0 = fmaf(fabsf(a0.y - b0.y), w0 - 1.0f, acc0);
        acc0 = fmaf(fabsf(a0.z - b0.z), w0 - 2.0f, acc0);
        acc0 = fmaf(fabsf(a0.w - b0.w), w0 - 3.0f, acc0);

        acc1 = fmaf(fabsf(a1.x - b1.x), w1,        acc1);
        acc1 = fmaf(fabsf(a1.y - b1.y), w1 - 1.0f, acc1);
        acc1 = fmaf(fabsf(a1.z - b1.z), w1 - 2.0f, acc1);
        acc1 = fmaf(fabsf(a1.w - b1.w), w1 - 3.0f, acc1);
    }
    if (i < n4) {
        float4 va = a[i];
        float4 vb = b[i];
        float w = (float)(T_DIM - ((i << 2) & (T_DIM - 1)));
        acc0 = fmaf(fabsf(va.x - vb.x), w,        acc0);
        acc0 = fmaf(fabsf(va.y - vb.y), w - 1.0f, acc0);
        acc0 = fmaf(fabsf(va.z - vb.z), w - 2.0f, acc0);
        acc0 = fmaf(fabsf(va.w - vb.w), w - 3.0f, acc0);
    }

    float acc = acc0 + acc1;

    #pragma unroll
    for (int o = 16; o > 0; o >>= 1)
        acc += __shfl_down_sync(0xffffffffu, acc, o);

    __shared__ float smem[8];
    const int lane = threadIdx.x & 31;
    const int wid  = threadIdx.x >> 5;
    if (lane == 0) smem[wid] = acc;
    __syncthreads();
    if (wid == 0) {
        acc = (lane < 8) ? smem[lane] : 0.0f;
        #pragma unroll
        for (int o = 4; o > 0; o >>= 1)
            acc += __shfl_down_sync(0xffffffffu, acc, o);

        if (lane == 0) {
            atomicAdd(&g_scratch, acc);
            __threadfence();
            unsigned int old = atomicAdd(&g_count, 1u);
            if (old == gridDim.x - 1) {
                out[0]    = g_scratch * scale;
                g_scratch = 0.0f;
                g_count   = 0u;
            }
        }
    }
}

extern "C" void kernel_launch(void* const* d_in, const int* in_sizes, int n_in,
                              void* d_out, int out_size) {
    const float4* y_pred = (const float4*)d_in[0];
    const float4* y_true = (const float4*)d_in[1];
    float* out = (float*)d_out;

    const int n  = in_sizes[0];   // 32*64*8192
    const int n4 = n / 4;

    const double T = (double)T_DIM;
    const double C = 64.0;
    const double B = (double)n / (T * C);
    const float scale = (float)(2.0 / (T * C * (T + 1.0) * B));

    // One full resident wave: 148 SMs x 8 CTAs x 256 thr = 64 warps/SM.
    const int threads = 256;
    int blocks = 148 * 8;
    int max_blocks = (n4 + threads - 1) / threads;
    if (blocks > max_blocks) blocks = max_blocks;

    wl_reduce<<<blocks, threads>>>(y_pred, y_true, out, n4, scale);
}